// round 2
// baseline (speedup 1.0000x reference)
#include <cuda_runtime.h>
#include <math.h>

#define BATCH 64
#define H 64
#define W 96
#define HW (H * W)
#define UV 81
#define NCH 16

#define BX 64       // pixels per block (2 warps per ty-row)
#define BY 3        // displacement chunks per pixel
#define CHUNK 27    // 81 / 3

// 1/ln(49), 1/ln(81)
#define INV_LN49 0.25694882f
#define INV_LN81 0.22756237f

__global__ __launch_bounds__(BX * BY) void segnet_flowreg_warp_kernel(
    const float* __restrict__ cost,
    const float* __restrict__ feat,
    float* __restrict__ out)
{
    __shared__ float s_max[BY][BX];
    __shared__ int   s_am [BY][BX];
    __shared__ float s_part[6][BY][BX];

    const int tx  = threadIdx.x;
    const int ty  = threadIdx.y;
    const int pix = blockIdx.x * BX + tx;      // b*HW + h*W + w
    const int b   = pix / HW;
    const int hw  = pix - b * HW;
    const int h   = hw / W;
    const int w   = hw - h * W;

    // ---- each ty loads its 27 cost slices (coalesced: lanes = consecutive hw) ----
    const float* cp = cost + (size_t)b * UV * HW + hw;
    float c[CHUNK];
    float m = -INFINITY;
    int   am = ty * CHUNK;
#pragma unroll
    for (int j = 0; j < CHUNK; j++) {
        float v = __ldg(cp + (size_t)(ty * CHUNK + j) * HW);
        c[j] = v;
        if (v > m) { m = v; am = ty * CHUNK + j; }  // strict > : first occurrence
    }
    s_max[ty][tx] = m;
    s_am [ty][tx] = am;
    __syncthreads();

    // ---- global max/argmax over the 3 chunks (chunk order preserves tie-break) ----
    float gm  = s_max[0][tx];
    int   gam = s_am [0][tx];
#pragma unroll
    for (int t = 1; t < BY; t++) {
        float v = s_max[t][tx];
        if (v > gm) { gm = v; gam = s_am[t][tx]; }
    }
    const int u0 = gam / 9;
    const int v0 = gam - 9 * u0;

    // ---- partial exp sums (window max == global max since argmax is in-window) ----
    float Sg = 0.f, Sg1 = 0.f;      // global: sum e, sum e*d
    float Sw = 0.f, Sw1 = 0.f;      // 7x7 window sums
    float Sx = 0.f, Sy = 0.f;       // window displacement moments
#pragma unroll
    for (int ul = 0; ul < 3; ul++) {
        const int u = ty * 3 + ul;
        const bool uin = (u - u0 <= 3) && (u0 - u <= 3);
#pragma unroll
        for (int v = 0; v < 9; v++) {
            float d = c[ul * 9 + v] - gm;
            float e = __expf(d);
            Sg  += e;
            Sg1 += e * d;
            bool inw = uin && (v - v0 <= 3) && (v0 - v <= 3);
            if (inw) {
                Sw  += e;
                Sw1 += e * d;
                Sx  += e * (float)(u - 4);
                Sy  += e * (float)(v - 4);
            }
        }
    }
    s_part[0][ty][tx] = Sg;  s_part[1][ty][tx] = Sg1;
    s_part[2][ty][tx] = Sw;  s_part[3][ty][tx] = Sw1;
    s_part[4][ty][tx] = Sx;  s_part[5][ty][tx] = Sy;
    __syncthreads();

    // ---- every thread combines (redundant but sync-free; conflict-free reads) ----
    Sg = 0.f; Sg1 = 0.f; Sw = 0.f; Sw1 = 0.f; Sx = 0.f; Sy = 0.f;
#pragma unroll
    for (int t = 0; t < BY; t++) {
        Sg  += s_part[0][t][tx];  Sg1 += s_part[1][t][tx];
        Sw  += s_part[2][t][tx];  Sw1 += s_part[3][t][tx];
        Sx  += s_part[4][t][tx];  Sy  += s_part[5][t][tx];
    }
    const float invSw = 1.0f / Sw;
    const float fx = Sx * invSw;                             // flow x = E[u-4]
    const float fy = Sy * invSw;                             // flow y = E[v-4]

    float* flow_o = out;
    float* ent_o  = out + (size_t)BATCH * 2 * HW;
    float* warp_o = out + (size_t)BATCH * 4 * HW;

    if (ty == 0) {
        const float lent = (logf(Sw) - Sw1 * invSw) * INV_LN49;
        const float gent = (logf(Sg) - Sg1 / Sg)    * INV_LN81;
        flow_o[((size_t)b * 2 + 0) * HW + hw] = fx;
        flow_o[((size_t)b * 2 + 1) * HW + hw] = fy;
        ent_o [((size_t)b * 2 + 0) * HW + hw] = lent;
        ent_o [((size_t)b * 2 + 1) * HW + hw] = gent;
    }

    // ---- bilinear backward warp (align_corners=True, zero pad); channels split over ty ----
    const float px = (float)w + fx;
    const float py = (float)h + fy;
    const float x0f = floorf(px), y0f = floorf(py);
    const float wx = px - x0f,   wy = py - y0f;
    const int x0 = (int)x0f, y0 = (int)y0f;
    const int x1 = x0 + 1,   y1 = y0 + 1;
    const bool vx0 = (x0 >= 0) & (x0 < W);
    const bool vx1 = (x1 >= 0) & (x1 < W);
    const bool vy0 = (y0 >= 0) & (y0 < H);
    const bool vy1 = (y1 >= 0) & (y1 < H);

    float w00 = (1.f - wx) * (1.f - wy) * ((vx0 & vy0) ? 1.f : 0.f);
    float w01 = wx         * (1.f - wy) * ((vx1 & vy0) ? 1.f : 0.f);
    float w10 = (1.f - wx) * wy         * ((vx0 & vy1) ? 1.f : 0.f);
    float w11 = wx         * wy         * ((vx1 & vy1) ? 1.f : 0.f);

    const float nx = 2.f * px / (float)(W - 1) - 1.f;
    const float ny = 2.f * py / (float)(H - 1) - 1.f;
    const float msk = (fabsf(nx) < 1.f && fabsf(ny) < 1.f) ? 1.f : 0.f;
    w00 *= msk; w01 *= msk; w10 *= msk; w11 *= msk;

    const int x0c = min(max(x0, 0), W - 1), x1c = min(max(x1, 0), W - 1);
    const int y0c = min(max(y0, 0), H - 1), y1c = min(max(y1, 0), H - 1);
    const int o00 = y0c * W + x0c, o01 = y0c * W + x1c;
    const int o10 = y1c * W + x0c, o11 = y1c * W + x1c;

    const float* fb = feat + (size_t)b * NCH * HW;
#pragma unroll
    for (int ch = ty; ch < NCH; ch += BY) {
        const float* f = fb + ch * HW;
        float val = w00 * __ldg(f + o00) + w01 * __ldg(f + o01)
                  + w10 * __ldg(f + o10) + w11 * __ldg(f + o11);
        warp_o[((size_t)b * NCH + ch) * HW + hw] = val;
    }
}

extern "C" void kernel_launch(void* const* d_in, const int* in_sizes, int n_in,
                              void* d_out, int out_size) {
    const float* cost = (const float*)d_in[0];
    const float* feat = (const float*)d_in[1];
    float* out = (float*)d_out;

    dim3 block(BX, BY);
    int blocks = (BATCH * HW) / BX;   // 6144
    segnet_flowreg_warp_kernel<<<blocks, block>>>(cost, feat, out);
}